// round 17
// baseline (speedup 1.0000x reference)
#include <cuda_runtime.h>
#include <cstdint>

// ----------------------------------------------------------------------------
// RNNDecoder: 3-layer GRU (H=128), T=256, B=1024, fc head (out=2).
//
// R15 = R14 (TMA ring: producer warp streams weights into smem, compute
// warps read via LDS) with 16 compute warps instead of 8 (K-quarter split):
// R14 proved the weight-latency theory (fma 55%, best yet) but 2 compute
// warps/SMSP leave TRYWAIT/LDS/combine chains exposed; 4 warps/SMSP
// interleave them. FMA floor unchanged (work conserved under K-split).
//   - 128 CTAs x 544 threads: warps 0-15 compute, warp 16 = producer.
//   - Merged accumulator (R12): hGEMV(i+1) re-inits acc{r,z,nh},
//     xGEMV(i) accumulates {r,z,nx} -> acc[4][4] = 32 regs (reg cap 120).
//   - Chunk = [2kk][3g][512t] float4 = 48KB; RING=3; full=1/empty=16 mbarriers.
//   - 4-way flat exchange (48KB, R8-style); 2 named barriers/cell.
// ----------------------------------------------------------------------------

namespace {
constexpr int LAYERS = 3;
constexpr int H      = 128;
constexpr int G3     = 3 * H;
constexpr int T      = 256;
constexpr int BC     = 8;
constexpr int NTHR   = 544;        // 16 compute warps + 1 producer warp
constexpr int CT     = 512;        // compute threads
constexpr int NBLK   = 128;        // 1024 / BC

constexpr int RING        = 3;
constexpr int CHUNK_BYTES = 49152; // 2 kk2 x 3 gates x 512 t x 16B
constexpr int CHUNK_F4    = 3072;
constexpr int NCID        = 24;    // (l, arr) x 4 chunks

// dynamic smem layout (bytes)
constexpr int SMEM_RING = 0;                              // 147456
constexpr int SMEM_X    = SMEM_RING + RING * CHUNK_BYTES; // float[1024] [k][b]
constexpr int SMEM_H    = SMEM_X + 4096;                  // float[3072] [l][k][b]
constexpr int SMEM_P    = SMEM_H + 12288;                 // ull[6144] exchange
constexpr int SMEM_BIAS = SMEM_P + 49152;                 // float[1536] [l][v][u]
constexpr int SMEM_FCW  = SMEM_BIAS + 6144;               // float[256]
constexpr int SMEM_FCB  = SMEM_FCW + 1024;                // float[2]
constexpr int SMEM_MBAR = SMEM_FCB + 16;                  // full[3], empty[3]
constexpr int SMEM_TOTAL = SMEM_MBAR + 64;                // 220240
}

typedef unsigned long long ull;

// Pre-transposed weights, chunk-contiguous:
// cid = (l*2 + arr)*4 + c ; within chunk: [kk2][g][t] float4,
// t = grp*128 + u (grp = K-quarter), absolute k4 = grp*8 + c*2 + kk2.
__device__ float4 g_wt[NCID * CHUNK_F4];

__global__ void prep_kernel(const float* __restrict__ wih,
                            const float* __restrict__ whh) {
  int idx = blockIdx.x * blockDim.x + threadIdx.x;
  if (idx >= NCID * CHUNK_F4) return;
  int cid = idx / CHUNK_F4;
  int e   = idx % CHUNK_F4;
  int t   = e & 511;
  int g   = (e >> 9) % 3;
  int kk2 = e / 1536;
  int c   = cid & 3;
  int la  = cid >> 2;
  int arr = la & 1, l = la >> 1;
  int grp = t >> 7, u = t & 127;
  int k4  = grp * 8 + c * 2 + kk2;
  const float* src =
      (arr ? whh : wih) + (l * G3 + g * 128 + u) * H + k4 * 4;
  g_wt[idx] = *reinterpret_cast<const float4*>(src);
}

__device__ __forceinline__ uint32_t smem_u32(const void* p) {
  uint32_t a;
  asm("{ .reg .u64 t; cvta.to.shared.u64 t, %1; cvt.u32.u64 %0, t; }"
      : "=r"(a) : "l"(p));
  return a;
}
#define MBAR_INIT(a, n) \
  asm volatile("mbarrier.init.shared.b64 [%0], %1;" :: "r"(a), "r"(n) : "memory")
#define MBAR_ARRIVE(a) \
  asm volatile("mbarrier.arrive.shared.b64 _, [%0];" :: "r"(a) : "memory")
#define MBAR_EXPECT_TX(a, n) \
  asm volatile("mbarrier.arrive.expect_tx.shared.b64 _, [%0], %1;" \
               :: "r"(a), "r"(n) : "memory")
#define BULK_G2S(dst, src, n, mbar) \
  asm volatile("cp.async.bulk.shared::cta.global.mbarrier::complete_tx::bytes" \
               " [%0], [%1], %2, [%3];" \
               :: "r"(dst), "l"(src), "r"(n), "r"(mbar) : "memory")
#define MBAR_WAITP(a, ph) do {                                              \
  uint32_t _d;                                                              \
  asm volatile("{\n\t.reg .pred p;\n\t"                                     \
    "mbarrier.try_wait.parity.acquire.cta.shared::cta.b64 p, [%1], %2;\n\t" \
    "selp.b32 %0, 1, 0, p;\n\t}"                                            \
    : "=r"(_d) : "r"(a), "r"(ph) : "memory");                               \
  while (!_d) {                                                             \
    asm volatile("{\n\t.reg .pred p;\n\t"                                   \
      "mbarrier.try_wait.parity.acquire.cta.shared::cta.b64 p, [%1], %2, 0x989680;\n\t" \
      "selp.b32 %0, 1, 0, p;\n\t}"                                          \
      : "=r"(_d) : "r"(a), "r"(ph) : "memory");                             \
  }                                                                         \
} while (0)

__device__ __forceinline__ void ffma2(ull& a, ull w, ull x) {
  asm("fma.rn.f32x2 %0, %1, %2, %0;" : "+l"(a) : "l"(w), "l"(x));
}
__device__ __forceinline__ void fadd2(ull& a, ull b) {
  asm("add.rn.f32x2 %0, %0, %1;" : "+l"(a) : "l"(b));
}
__device__ __forceinline__ ull dup2(float w) {
  ull r;
  asm("mov.b64 %0, {%1, %1};" : "=l"(r) : "f"(w));
  return r;
}
__device__ __forceinline__ float2 unpk(ull v) {
  float lo, hi;
  asm("mov.b64 {%0, %1}, %2;" : "=f"(lo), "=f"(hi) : "l"(v));
  return make_float2(lo, hi);
}
__device__ __forceinline__ ull pack2(float lo, float hi) {
  ull r;
  asm("mov.b64 %0, {%1, %2};" : "=l"(r) : "f"(lo), "f"(hi));
  return r;
}
__device__ __forceinline__ float sigm(float x) {
  return __fdividef(1.0f, 1.0f + __expf(-x));
}
__device__ __forceinline__ float tanh_fast(float v) {
  float a = fabsf(v);
  float e = __expf(-2.0f * a);
  float r = __fdividef(1.0f - e, 1.0f + e);
  return copysignf(r, v);
}
__device__ __forceinline__ float comp(const float4& v, int e) {
  return e == 0 ? v.x : e == 1 ? v.y : e == 2 ? v.z : v.w;
}
__device__ __forceinline__ void cbar() {           // compute-warps barrier
  asm volatile("bar.sync 1, %0;" :: "r"(CT) : "memory");
}

// One array's gemv over this thread's K-quarter, consuming 4 ring chunks.
// Merged accumulator: rows {0:r, 1:z} shared by both arrays;
// ARR=1 (W_hh, pipelined for next cell): zero-inits acc, fills rows {0,1,3}.
// ARR=0 (W_ih, current cell): accumulates rows {0,1}, fills row 2.
template <int ARR>
__device__ __forceinline__ void gemv_ring(char* dsm,
                                          const float* __restrict__ act,
                                          int t, int& cs, int& cp,
                                          ull (&acc)[4][4]) {
  if (ARR == 1) {
#pragma unroll
    for (int g = 0; g < 4; g++)
#pragma unroll
      for (int q = 0; q < 4; q++) acc[g][q] = 0ull;
  }
  const uint32_t mb0 = smem_u32(dsm + SMEM_MBAR);
  const int NROW = (ARR == 0) ? 2 : 3;
#pragma unroll
  for (int c = 0; c < 4; c++) {
    MBAR_WAITP(mb0 + cs * 8, cp);                  // full[cs]
    const float4* wb = reinterpret_cast<const float4*>(
        dsm + SMEM_RING + cs * CHUNK_BYTES);
#pragma unroll
    for (int kk2 = 0; kk2 < 2; kk2++) {
      float4 w0 = wb[(kk2 * 3 + 0) * 512 + t];
      float4 w1 = wb[(kk2 * 3 + 1) * 512 + t];
      float4 w2 = wb[(kk2 * 3 + 2) * 512 + t];
#pragma unroll
      for (int e = 0; e < 4; e++) {
        int k8 = ((c * 2 + kk2) * 4 + e) * 8;
        ulonglong2 v0 = *reinterpret_cast<const ulonglong2*>(act + k8);
        ulonglong2 v1 = *reinterpret_cast<const ulonglong2*>(act + k8 + 4);
        ull wr = dup2(comp(w0, e));
        ffma2(acc[0][0], wr, v0.x); ffma2(acc[0][1], wr, v0.y);
        ffma2(acc[0][2], wr, v1.x); ffma2(acc[0][3], wr, v1.y);
        ull wz = dup2(comp(w1, e));
        ffma2(acc[1][0], wz, v0.x); ffma2(acc[1][1], wz, v0.y);
        ffma2(acc[1][2], wz, v1.x); ffma2(acc[1][3], wz, v1.y);
        ull wn = dup2(comp(w2, e));
        ffma2(acc[NROW][0], wn, v0.x); ffma2(acc[NROW][1], wn, v0.y);
        ffma2(acc[NROW][2], wn, v1.x); ffma2(acc[NROW][3], wn, v1.y);
      }
    }
    if ((threadIdx.x & 31) == 0)
      MBAR_ARRIVE(mb0 + 24 + cs * 8);              // empty[cs], count=16
    cs++;
    if (cs == RING) { cs = 0; cp ^= 1; }
  }
}

// Combine owned pair P: add 3 partner contributions, GRU gate math, write h.
template <int P>
__device__ __forceinline__ void combine_own(const ull (&acc)[4][4],
                                            const ull* __restrict__ sp, int u,
                                            const float* __restrict__ sb,
                                            float* __restrict__ hl,
                                            float* __restrict__ sx) {
  ull r2 = acc[0][P], z2 = acc[1][P], nx2 = acc[2][P], nh2 = acc[3][P];
#pragma unroll
  for (int c = 0; c < 3; c++) {
    const ull* base = sp + ((P * 3 + c) * 4) * 128 + u;
    fadd2(r2,  base[0]);
    fadd2(z2,  base[128]);
    fadd2(nx2, base[256]);
    fadd2(nh2, base[384]);
  }
  float brz_r = sb[u], brz_z = sb[128 + u];
  float bn_x = sb[256 + u], bn_h = sb[384 + u];
  float2 rr = unpk(r2), zz = unpk(z2), xx = unpk(nx2), hh = unpk(nh2);
  float2 hp = unpk(*reinterpret_cast<const ull*>(hl + u * 8 + 2 * P));
  float r0 = sigm(rr.x + brz_r), z0 = sigm(zz.x + brz_z);
  float n0 = tanh_fast(xx.x + bn_x + r0 * (hh.x + bn_h));
  float h0 = fmaf(z0, hp.x - n0, n0);
  float r1 = sigm(rr.y + brz_r), z1 = sigm(zz.y + brz_z);
  float n1 = tanh_fast(xx.y + bn_x + r1 * (hh.y + bn_h));
  float h1 = fmaf(z1, hp.y - n1, n1);
  ull o = pack2(h0, h1);
  *reinterpret_cast<ull*>(hl + u * 8 + 2 * P) = o;
  *reinterpret_cast<ull*>(sx + u * 8 + 2 * P) = o;
}

__global__ void __launch_bounds__(NTHR, 1)
gru_kernel(const float* __restrict__ hiddens,
           const float* __restrict__ b_ih,
           const float* __restrict__ b_hh,
           const float* __restrict__ fc_w,
           const float* __restrict__ fc_b,
           float* __restrict__ out) {
  extern __shared__ __align__(16) char dsm[];
  float* s_x    = reinterpret_cast<float*>(dsm + SMEM_X);
  float* s_h    = reinterpret_cast<float*>(dsm + SMEM_H);
  ull*   s_p    = reinterpret_cast<ull*>(dsm + SMEM_P);
  float* s_bias = reinterpret_cast<float*>(dsm + SMEM_BIAS);
  float* s_fcw  = reinterpret_cast<float*>(dsm + SMEM_FCW);
  float* s_fcb  = reinterpret_cast<float*>(dsm + SMEM_FCB);
  const uint32_t mb0 = smem_u32(dsm + SMEM_MBAR);

  const int tid = threadIdx.x;
  const int b0  = blockIdx.x * BC;

  // ---- shared init (all 544 threads) ----
  if (tid < 128) {
#pragma unroll
    for (int l = 0; l < LAYERS; l++) {
      s_bias[l * 512 + 0 * 128 + tid] =
          b_ih[l * G3 + tid] + b_hh[l * G3 + tid];
      s_bias[l * 512 + 1 * 128 + tid] =
          b_ih[l * G3 + 128 + tid] + b_hh[l * G3 + 128 + tid];
      s_bias[l * 512 + 2 * 128 + tid] = b_ih[l * G3 + 256 + tid];
      s_bias[l * 512 + 3 * 128 + tid] = b_hh[l * G3 + 256 + tid];
    }
  }
  if (tid < 256) s_fcw[tid] = fc_w[tid];
  if (tid < 2)   s_fcb[tid] = fc_b[tid];
  for (int i = tid; i < LAYERS * H * BC; i += NTHR) {
    int l = i >> 10, rem = i & 1023, k = rem >> 3, b = rem & 7;
    s_h[i] = hiddens[(b0 + b) * (LAYERS * H) + l * H + k];
  }
  for (int i = tid; i < H * BC; i += NTHR) s_x[i] = 0.0f;
  if (tid == 0) {
#pragma unroll
    for (int s = 0; s < RING; s++) {
      MBAR_INIT(mb0 + s * 8, 1);            // full[s]: producer expect_tx
      MBAR_INIT(mb0 + 24 + s * 8, 16);      // empty[s]: 16 compute warps
    }
  }
  __syncthreads();

  if (tid >= CT) {
    // ---------------- producer warp ----------------
    if ((tid & 31) == 0) {
      int ps = 0, pp = 1;                   // producer cursor, phase 1
      const char* gw = reinterpret_cast<const char*>(g_wt);
      const uint32_t ring0 = smem_u32(dsm + SMEM_RING);
      // prologue: W_hh layer 0 (cid base 4)
      for (int c = 0; c < 4; c++) {
        MBAR_WAITP(mb0 + 24 + ps * 8, pp);
        MBAR_EXPECT_TX(mb0 + ps * 8, (uint32_t)CHUNK_BYTES);
        BULK_G2S(ring0 + ps * CHUNK_BYTES,
                 (uint64_t)(gw + (4 + c) * CHUNK_BYTES),
                 (uint32_t)CHUNK_BYTES, mb0 + ps * 8);
        if (++ps == RING) { ps = 0; pp ^= 1; }
      }
      for (int t = 0; t < T; t++) {
        for (int l = 0; l < LAYERS; l++) {
          int ln = (l == LAYERS - 1) ? 0 : l + 1;
          for (int j = 0; j < 8; j++) {
            int cid = (j < 4) ? (l * 8 + j) : (ln * 8 + 4 + (j - 4));
            MBAR_WAITP(mb0 + 24 + ps * 8, pp);
            MBAR_EXPECT_TX(mb0 + ps * 8, (uint32_t)CHUNK_BYTES);
            BULK_G2S(ring0 + ps * CHUNK_BYTES,
                     (uint64_t)(gw + cid * CHUNK_BYTES),
                     (uint32_t)CHUNK_BYTES, mb0 + ps * 8);
            if (++ps == RING) { ps = 0; pp ^= 1; }
          }
        }
      }
    }
    return;
  }

  // ---------------- compute warps (tid 0..511) ----------------
  const int u   = tid & 127;
  const int grp = tid >> 7;                 // K-quarter & owned batch-pair
  int cs = 0, cp = 0;                       // consumer ring cursor

  // Prologue: W_hh gemv of cell 0 (layer 0) initializes acc.
  ull acc[4][4];
  gemv_ring<1>(dsm, s_h + grp * 256, tid, cs, cp, acc);

  for (int t = 0; t < T; t++) {
#pragma unroll 1
    for (int l = 0; l < LAYERS; l++) {
      float* __restrict__ hl = s_h + l * (H * BC);

      // W_ih gemv of the current cell accumulates into acc.
      gemv_ring<0>(dsm, s_x + grp * 256, tid, cs, cp, acc);

      // Store partials for the 3 batch-pairs this group does not own.
#pragma unroll
      for (int q = 0; q < 4; q++) {
        if (q == grp) continue;             // runtime guard, const q
        int c = grp - (grp > q ? 1 : 0);
        ull* base = s_p + ((q * 3 + c) * 4) * 128 + u;
        base[0]   = acc[0][q];
        base[128] = acc[1][q];
        base[256] = acc[2][q];
        base[384] = acc[3][q];
      }
      cbar();                               // B1: partials visible

      // combine(i), then pipelined W_hh gemv for the next cell (re-inits acc).
      const float* sb = s_bias + l * 512;
      if (grp == 0)      combine_own<0>(acc, s_p, u, sb, hl, s_x);
      else if (grp == 1) combine_own<1>(acc, s_p, u, sb, hl, s_x);
      else if (grp == 2) combine_own<2>(acc, s_p, u, sb, hl, s_x);
      else               combine_own<3>(acc, s_p, u, sb, hl, s_x);

      int ln = (l == LAYERS - 1) ? 0 : l + 1;
      gemv_ring<1>(dsm, s_h + ln * (H * BC) + grp * 256, tid, cs, cp, acc);
      cbar();                               // B2: s_x visible

      // fc head: 16 outputs (2 out x 8 batch) x 16 lanes.
      if (l == 2 && tid < 256) {
        int oid = tid >> 4, s = tid & 15;
        int o = oid & 1, b = oid >> 1;
        float p = 0.0f;
#pragma unroll
        for (int m = 0; m < 8; m++)
          p = fmaf(s_fcw[o * H + s * 8 + m], s_x[(s * 8 + m) * 8 + b], p);
        p += __shfl_down_sync(0xffffffffu, p, 8, 16);
        p += __shfl_down_sync(0xffffffffu, p, 4, 16);
        p += __shfl_down_sync(0xffffffffu, p, 2, 16);
        p += __shfl_down_sync(0xffffffffu, p, 1, 16);
        if (s == 0) out[((b0 + b) * T + t) * 2 + o] = p + s_fcb[o];
      }
      // fc reads of s_x precede the next cell's combine writes (those sit
      // behind the next cell's B1).
    }
  }
}

extern "C" void kernel_launch(void* const* d_in, const int* in_sizes, int n_in,
                              void* d_out, int out_size) {
  (void)in_sizes; (void)n_in; (void)out_size;
  const float* hiddens = (const float*)d_in[0];
  const float* W_ih    = (const float*)d_in[1];
  const float* W_hh    = (const float*)d_in[2];
  const float* b_ih    = (const float*)d_in[3];
  const float* b_hh    = (const float*)d_in[4];
  const float* fc_w    = (const float*)d_in[5];
  const float* fc_b    = (const float*)d_in[6];
  float* out = (float*)d_out;

  cudaFuncSetAttribute(gru_kernel, cudaFuncAttributeMaxDynamicSharedMemorySize,
                       SMEM_TOTAL);

  const int prep_elems = NCID * CHUNK_F4;
  prep_kernel<<<(prep_elems + 255) / 256, 256>>>(W_ih, W_hh);
  gru_kernel<<<NBLK, NTHR, SMEM_TOTAL>>>(hiddens, b_ih, b_hh, fc_w, fc_b, out);
}